// round 6
// baseline (speedup 1.0000x reference)
#include <cuda_runtime.h>
#include <math.h>

#define B_NO   8
#define T_LEN  10000
#define E_NUM  1000
#define I_NUM  250
#define SUB_NO 8
#define HID_NO 16
#define CBAS   30
#define T_NO   200

// output layout: final | sub_out | C_syn_e | C_syn_i
#define FINAL_OFF  0
#define SUBOUT_OFF (B_NO * T_LEN)                       // 80000
#define CE_OFF     (SUBOUT_OFF + B_NO * T_LEN * SUB_NO) // 720000
#define CI_OFF     (CE_OFF + SUB_NO * E_NUM)            // 728000

// ---------------- device scratch ----------------
__device__ float g_kern_e[SUB_NO * T_NO * HID_NO];     // [s][tau][h]
__device__ float g_kern_i[SUB_NO * T_NO * HID_NO];
__device__ float g_syn_e[B_NO * SUB_NO * T_LEN];       // [b][s][t]
__device__ float g_syn_i[B_NO * SUB_NO * T_LEN];
// transposed+swizzled scaled C matrices
// E: 256 e4-rows x 8 float4 (float4 j = (ee*2+half)^(e4&7); holds s=4*half..4*half+3 at e=e4*4+ee)
__device__ float4 g_CeT[256 * 8];
// I: [e][10] floats (sp*2 + comp), e < 256, zero padded
__device__ float4 g_CiT4[640];   // 2560 floats

// ---------------- helpers ----------------
__device__ __forceinline__ float2 ffma2(float2 a, float2 b, float2 c) {
    union U { float2 f; unsigned long long u; };
    U A, B, C, D;
    A.f = a; B.f = b; C.f = c;
    asm("fma.rn.f32x2 %0, %1, %2, %3;" : "=l"(D.u) : "l"(A.u), "l"(B.u), "l"(C.u));
    return D.f;
}

__device__ __forceinline__ float tanh_fast(float x) {
    float e = __expf(2.0f * x);
    return 1.0f - __fdividef(2.0f, e + 1.0f);
}

__device__ __forceinline__ float2 shfl_xor_f2(float2 v, int m) {
    union { float2 f; double d; } u;
    u.f = v;
    u.d = __shfl_xor_sync(0xffffffffu, u.d, m);
    return u.f;
}

// ---------------- K-1: zero the transposed C scratch ----------------
__global__ void init_ct_kernel() {
    int idx = blockIdx.x * blockDim.x + threadIdx.x;
    float4 z = make_float4(0.f, 0.f, 0.f, 0.f);
    if (idx < 2048) g_CeT[idx] = z;
    if (idx < 640)  g_CiT4[idx] = z;
}

// ---------------- K0: softmax + scaled transposed copies ----------------
__global__ void softmax_kernel(const float* __restrict__ Cer,
                               const float* __restrict__ Cir,
                               const float* __restrict__ Es,
                               const float* __restrict__ Is,
                               float* __restrict__ out) {
    int idx = blockIdx.x * blockDim.x + threadIdx.x;
    if (idx < E_NUM) {
        float u[SUB_NO], p[SUB_NO], sc_v[SUB_NO];
        float m = -1e30f;
#pragma unroll
        for (int s = 0; s < SUB_NO; ++s) { u[s] = Cer[s * E_NUM + idx] * 10000.0f; m = fmaxf(m, u[s]); }
        float sum = 0.0f;
#pragma unroll
        for (int s = 0; s < SUB_NO; ++s) { p[s] = expf(u[s] - m); sum += p[s]; }
        float inv = 1.0f / sum;
        float sc  = expf(Es[idx]);
#pragma unroll
        for (int s = 0; s < SUB_NO; ++s) {
            float v = p[s] * inv;
            out[CE_OFF + s * E_NUM + idx] = v;
            sc_v[s] = v * sc;
        }
        int e4 = idx >> 2, ee = idx & 3, swz = e4 & 7;
#pragma unroll
        for (int half = 0; half < 2; ++half) {
            int phys = e4 * 8 + ((ee * 2 + half) ^ swz);
            g_CeT[phys] = make_float4(sc_v[half * 4 + 0], sc_v[half * 4 + 1],
                                      sc_v[half * 4 + 2], sc_v[half * 4 + 3]);
        }
    } else if (idx < E_NUM + I_NUM) {
        int j = idx - E_NUM;
        float u[SUB_NO], p[SUB_NO];
        float m = -1e30f;
#pragma unroll
        for (int s = 0; s < SUB_NO; ++s) { u[s] = Cir[s * I_NUM + j] * 10000.0f; m = fmaxf(m, u[s]); }
        float sum = 0.0f;
#pragma unroll
        for (int s = 0; s < SUB_NO; ++s) { p[s] = expf(u[s] - m); sum += p[s]; }
        float inv = 1.0f / sum;
        float sc  = expf(Is[j]);
        float* ct = (float*)g_CiT4;
#pragma unroll
        for (int s = 0; s < SUB_NO; ++s) {
            float v = p[s] * inv;
            out[CI_OFF + s * I_NUM + j] = v;
            ct[j * 10 + s] = v * sc;   // s = sp*2 + comp layout (s0..s7 contiguous)
        }
    }
}

// ---------------- K1: temporal kernels from cosine basis ----------------
__global__ void kern_kernel(const float* __restrict__ W_e,
                            const float* __restrict__ W_i) {
    __shared__ float bas[CBAS];
    int tau = blockIdx.x;
    if (threadIdx.x < CBAS) {
        double phi = 0.5 * M_PI * (double)threadIdx.x;
        double raw = 7.5 * log((double)tau + 1.0 + 1e-7);
        double v = 0.0;
        if (raw >= phi - M_PI && raw <= phi + M_PI)
            v = 0.5 * cos(raw - phi) + 0.5;
        bas[threadIdx.x] = (float)v;
    }
    __syncthreads();
    int r = threadIdx.x;             // 0..127
    float ae = 0.0f, ai = 0.0f;
#pragma unroll
    for (int c = 0; c < CBAS; ++c) {
        ae = fmaf(W_e[r * CBAS + c], bas[c], ae);
        ai = fmaf(W_i[r * CBAS + c], bas[c], ai);
    }
    int s = r >> 4, h = r & 15;
    g_kern_e[(s * T_NO + tau) * HID_NO + h] = ae;
    g_kern_i[(s * T_NO + tau) * HID_NO + h] = ai;
}

// ---------------- K2: synapse pooling (HBM-bound, persistent blocks) ----------------
#define POOL_BLK_X 37
#define N_TILES    313          // ceil(10000/32)

__global__ void __launch_bounds__(256)
pool_kernel(const float* __restrict__ S_e, const float* __restrict__ S_i) {
    __shared__ float4 shCe[256 * 8];   // 32KB, same swizzled layout as g_CeT
    __shared__ float  shCi[2560];      // 10KB, [e][10]

    int tid = threadIdx.x;
    for (int i = tid; i < 2048; i += 256) shCe[i] = g_CeT[i];
    for (int i = tid; i < 640; i += 256) ((float4*)shCi)[i] = g_CiT4[i];
    __syncthreads();

    int b = blockIdx.y;
    int warp = tid >> 5, lane = tid & 31;
    size_t rowE0 = (size_t)b * T_LEN;
    float* dstE = &g_syn_e[b * SUB_NO * T_LEN];
    float* dstI = &g_syn_i[b * SUB_NO * T_LEN];

    for (int tile = blockIdx.x; tile < N_TILES; tile += POOL_BLK_X) {
        int t0 = tile * 32 + warp * 4;

        float2 acc[4][4];
#pragma unroll
        for (int r = 0; r < 4; ++r)
#pragma unroll
            for (int sp = 0; sp < 4; ++sp) acc[r][sp] = make_float2(0.f, 0.f);

        // ---- excitatory: chunks of 128 e ----
#pragma unroll 1
        for (int chunk = 0; chunk < 8; ++chunk) {
            int e = chunk * 128 + lane * 4;
            float4 sv[4];
#pragma unroll
            for (int r = 0; r < 4; ++r) {
                int t = t0 + r;
                sv[r] = (t < T_LEN && e < E_NUM)
                        ? __ldg((const float4*)(S_e + (rowE0 + t) * E_NUM + e))
                        : make_float4(0.f, 0.f, 0.f, 0.f);
            }
            int e4 = chunk * 32 + lane;
            int swz = e4 & 7;
            const float4* she = &shCe[e4 * 8];
#pragma unroll
            for (int ee = 0; ee < 4; ++ee) {
                float4 cA = she[(ee * 2 + 0) ^ swz];
                float4 cB = she[(ee * 2 + 1) ^ swz];
                float2 c0 = make_float2(cA.x, cA.y), c1 = make_float2(cA.z, cA.w);
                float2 c2 = make_float2(cB.x, cB.y), c3 = make_float2(cB.z, cB.w);
#pragma unroll
                for (int r = 0; r < 4; ++r) {
                    float x = (ee == 0) ? sv[r].x : (ee == 1) ? sv[r].y : (ee == 2) ? sv[r].z : sv[r].w;
                    float2 vv = make_float2(x, x);
                    acc[r][0] = ffma2(c0, vv, acc[r][0]);
                    acc[r][1] = ffma2(c1, vv, acc[r][1]);
                    acc[r][2] = ffma2(c2, vv, acc[r][2]);
                    acc[r][3] = ffma2(c3, vv, acc[r][3]);
                }
            }
        }
        // reduce + write E
        {
#pragma unroll
            for (int st = 16; st >= 1; st >>= 1)
#pragma unroll
                for (int r = 0; r < 4; ++r)
#pragma unroll
                    for (int sp = 0; sp < 4; ++sp) {
                        float2 o = shfl_xor_f2(acc[r][sp], st);
                        acc[r][sp].x += o.x; acc[r][sp].y += o.y;
                    }
            int i = lane >> 3, s = lane & 7;
            int t = t0 + i;
            if (t < T_LEN) {
                float2 v2 = acc[i][s >> 1];
                dstE[s * T_LEN + t] = (s & 1) ? v2.y : v2.x;
            }
        }

        // ---- inhibitory: chunks of 64 e (32 float2) ----
#pragma unroll
        for (int r = 0; r < 4; ++r)
#pragma unroll
            for (int sp = 0; sp < 4; ++sp) acc[r][sp] = make_float2(0.f, 0.f);

#pragma unroll 1
        for (int chunk = 0; chunk < 4; ++chunk) {
            int p = chunk * 32 + lane;       // float2 index
            float2 sv[4];
#pragma unroll
            for (int r = 0; r < 4; ++r) {
                int t = t0 + r;
                sv[r] = (t < T_LEN && p < 125)
                        ? __ldg((const float2*)(S_i + (rowE0 + t) * I_NUM + p * 2))
                        : make_float2(0.f, 0.f);
            }
#pragma unroll
            for (int ee = 0; ee < 2; ++ee) {
                int e = p * 2 + ee;
                const float* ci = &shCi[e * 10];
                float2 c0 = *(const float2*)(ci + 0);
                float2 c1 = *(const float2*)(ci + 2);
                float2 c2 = *(const float2*)(ci + 4);
                float2 c3 = *(const float2*)(ci + 6);
#pragma unroll
                for (int r = 0; r < 4; ++r) {
                    float x = ee ? sv[r].y : sv[r].x;
                    float2 vv = make_float2(x, x);
                    acc[r][0] = ffma2(c0, vv, acc[r][0]);
                    acc[r][1] = ffma2(c1, vv, acc[r][1]);
                    acc[r][2] = ffma2(c2, vv, acc[r][2]);
                    acc[r][3] = ffma2(c3, vv, acc[r][3]);
                }
            }
        }
        // reduce + write I
        {
#pragma unroll
            for (int st = 16; st >= 1; st >>= 1)
#pragma unroll
                for (int r = 0; r < 4; ++r)
#pragma unroll
                    for (int sp = 0; sp < 4; ++sp) {
                        float2 o = shfl_xor_f2(acc[r][sp], st);
                        acc[r][sp].x += o.x; acc[r][sp].y += o.y;
                    }
            int i = lane >> 3, s = lane & 7;
            int t = t0 + i;
            if (t < T_LEN) {
                float2 v2 = acc[i][s >> 1];
                dstI[s * T_LEN + t] = (s & 1) ? v2.y : v2.x;
            }
        }
    }
}

// ---------------- K3: causal conv + tanh + readout (fma-bound) ----------------
#define TC 512
#define XW (TC + T_NO)   // 712

__global__ void __launch_bounds__(128)
conv_kernel(const float* __restrict__ W2,
            const float* __restrict__ b1,
            float* __restrict__ out) {
    __shared__ __align__(16) float4 sKe[T_NO * 4];   // [tau][4] float4 = 16 h
    __shared__ __align__(16) float4 sKi[T_NO * 4];
    __shared__ float sXe[XW], sXi[XW];
    __shared__ float sEw2[HID_NO], sB1[HID_NO];

    int tid = threadIdx.x;
    int bs = blockIdx.y;
    int b = bs >> 3, s = bs & 7;
    int t0 = blockIdx.x * TC;

    const float4* ge = (const float4*)g_kern_e + s * (T_NO * 4);
    const float4* gi = (const float4*)g_kern_i + s * (T_NO * 4);
    for (int idx = tid; idx < T_NO * 4; idx += 128) {
        sKe[idx] = ge[idx];
        sKi[idx] = gi[idx];
    }
    for (int idx = tid; idx < XW; idx += 128) {
        int g = t0 - (T_NO - 1) + idx;
        bool ok = (g >= 0) && (g < T_LEN);
        sXe[idx] = ok ? g_syn_e[(b * SUB_NO + s) * T_LEN + g] : 0.0f;
        sXi[idx] = ok ? g_syn_i[(b * SUB_NO + s) * T_LEN + g] : 0.0f;
    }
    if (tid < HID_NO) {
        sEw2[tid] = expf(W2[s * HID_NO + tid]);
        sB1[tid]  = b1[s * HID_NO + tid];
    }
    __syncthreads();

    float2 acc[4][8];
#pragma unroll
    for (int r = 0; r < 4; ++r)
#pragma unroll
        for (int hp = 0; hp < 8; ++hp) acc[r][hp] = make_float2(0.f, 0.f);

    int o0 = tid + (T_NO - 1);

#pragma unroll 2
    for (int tau = 0; tau < T_NO; ++tau) {
        float4 ke[4], ki[4];
#pragma unroll
        for (int q = 0; q < 4; ++q) { ke[q] = sKe[tau * 4 + q]; ki[q] = sKi[tau * 4 + q]; }
        float xe[4], xi[4];
#pragma unroll
        for (int r = 0; r < 4; ++r) { xe[r] = sXe[o0 + r * 128 - tau]; xi[r] = sXi[o0 + r * 128 - tau]; }
#pragma unroll
        for (int r = 0; r < 4; ++r) {
            float2 ve = make_float2(xe[r], xe[r]);
            float2 vi = make_float2(xi[r], xi[r]);
#pragma unroll
            for (int q = 0; q < 4; ++q) {
                acc[r][2*q]   = ffma2(make_float2(ke[q].x, ke[q].y), ve, acc[r][2*q]);
                acc[r][2*q+1] = ffma2(make_float2(ke[q].z, ke[q].w), ve, acc[r][2*q+1]);
                acc[r][2*q]   = ffma2(make_float2(ki[q].x, ki[q].y), vi, acc[r][2*q]);
                acc[r][2*q+1] = ffma2(make_float2(ki[q].z, ki[q].w), vi, acc[r][2*q+1]);
            }
        }
    }

    // epilogue: tanh + positive readout -> sub_out[b, t, s]
#pragma unroll
    for (int r = 0; r < 4; ++r) {
        int t = t0 + tid + r * 128;
        if (t < T_LEN) {
            float so = 0.0f;
#pragma unroll
            for (int hp = 0; hp < 8; ++hp) {
                so = fmaf(sEw2[2*hp],   tanh_fast(acc[r][hp].x + sB1[2*hp]),   so);
                so = fmaf(sEw2[2*hp+1], tanh_fast(acc[r][hp].y + sB1[2*hp+1]), so);
            }
            out[SUBOUT_OFF + (size_t)(b * T_LEN + t) * SUB_NO + s] = so;
        }
    }
}

// ---------------- K4: final = sum_s sub_out + V_o ----------------
__global__ void final_kernel(const float* __restrict__ V_o, float* __restrict__ out) {
    int idx = blockIdx.x * blockDim.x + threadIdx.x;
    if (idx >= B_NO * T_LEN) return;
    const float4* p = (const float4*)&out[SUBOUT_OFF + (size_t)idx * SUB_NO];
    float4 a = p[0], c = p[1];
    out[FINAL_OFF + idx] = V_o[0] + ((a.x + a.y) + (a.z + a.w)) + ((c.x + c.y) + (c.z + c.w));
}

// ---------------- launch ----------------
extern "C" void kernel_launch(void* const* d_in, const int* in_sizes, int n_in,
                              void* d_out, int out_size) {
    (void)in_sizes; (void)n_in; (void)out_size;
    const float* S_e   = (const float*)d_in[0];
    const float* S_i   = (const float*)d_in[1];
    const float* Es    = (const float*)d_in[2];
    const float* Is    = (const float*)d_in[3];
    const float* W_e   = (const float*)d_in[4];
    const float* W_i   = (const float*)d_in[5];
    const float* W2    = (const float*)d_in[6];
    const float* b1    = (const float*)d_in[7];
    const float* Cer   = (const float*)d_in[8];
    const float* Cir   = (const float*)d_in[9];
    const float* V_o   = (const float*)d_in[10];
    float* out = (float*)d_out;

    init_ct_kernel<<<8, 256>>>();
    softmax_kernel<<<(E_NUM + I_NUM + 255) / 256, 256>>>(Cer, Cir, Es, Is, out);
    kern_kernel<<<T_NO, 128>>>(W_e, W_i);

    dim3 pg(POOL_BLK_X, B_NO);             // 37 x 8 persistent-ish blocks
    pool_kernel<<<pg, 256>>>(S_e, S_i);

    dim3 cg((T_LEN + TC - 1) / TC, B_NO * SUB_NO);  // 20 x 64
    conv_kernel<<<cg, 128>>>(W2, b1, out);

    final_kernel<<<(B_NO * T_LEN + 255) / 256, 256>>>(V_o, out);
}